// round 11
// baseline (speedup 1.0000x reference)
#include <cuda_runtime.h>
#include <cuda_bf16.h>
#include <mma.h>
#include <cstdint>

using namespace nvcuda;

// ---------------------------------------------------------------------------
// ContrastiveSparsityLoss — wmma bf16-split (HMMA) conv + GEMM.
// tcgen05 is unavailable: harness compiles PTX for target sm_103 (no 'a'
// feature set). mma.sync/wmma bf16 is base-PTX and runs on the tensor pipe.
//
// Per encode (path in {sparse,dense} x g in {g1,g2,g3}):
//   K1 conv3x3  : x[5,C,256,256] -> g_y1[5,64,256,256]   (wmma, 3-term split)
//   K2 rowstat  : per-(n,o) sum/sumsq of y1
//   K3 bncoef   : BN1 scale/bias (per-sample sparse, pooled dense)
//   K4 gemm     : z = w2 @ relu(bn1(y1)) -> g_z          (wmma, 3-term split)
//   K5 rowstat  : per-(n,oc) sum/sumsq of z
//   K6 bncoef   : BN2 scale/bias
//   K7 feat     : feat[n,oc] = mean_pix relu(bn2(z))
// Then one single-block loss kernel.
// ---------------------------------------------------------------------------

__device__ float g_y1[5 * 64 * 65536];    // 83.9 MB scratch
__device__ float g_z [5 * 128 * 65536];   // 167.8 MB scratch
__device__ float g_stat1[5 * 64 * 2];
__device__ float g_stat2[5 * 128 * 2];
__device__ float g_a1[5 * 64];
__device__ float g_b1[5 * 64];
__device__ float g_a2[5 * 128];
__device__ float g_b2[5 * 128];
__device__ float g_feat[6 * 5 * 128];     // [e][n][oc], e = path*3+g

__device__ __forceinline__ void split_bf16(float v, __nv_bfloat16& hi, __nv_bfloat16& lo) {
    hi = __float2bfloat16(v);
    lo = __float2bfloat16(v - __bfloat162float(hi));
}

// ---------------------------------------------------------------------------
// K1: conv3x3 SAME via wmma. Block = 64 oc x 16x16 pixel tile of one sample.
// 8 warps; warp owns 2 y-rows x all 64 oc. For each (dy,dx) kernel tap the
// conv is a [x16 x ci16] @ [ci16 x oc16] GEMM on a shifted patch window.
//
// Patch layout [yy][xx][ci16] (ci innermost): fragment A (m=x, k=ci) has
// lda=16 and base ptr sP + ((y+dy)*18 + dx)*16 — 32B-aligned for every shift.
// Weights staged [dydx][ci16][oc64] (ld=64) as fragment B (k=ci, n=oc).
// 3-term bf16 split: acc += Ah*Bh + Ah*Bl + Al*Bh.
// ---------------------------------------------------------------------------
__global__ __launch_bounds__(256) void conv3x3_wmma_kernel(
    const float* __restrict__ x, const float* __restrict__ w, int Cin)
{
    extern __shared__ char dynsmem[];
    __nv_bfloat16* sPh = reinterpret_cast<__nv_bfloat16*>(dynsmem);   // [18][18][16]
    __nv_bfloat16* sPl = sPh + 18 * 18 * 16;                          // 5184 each
    __nv_bfloat16* sWh = sPl + 18 * 18 * 16;                          // [9][16][64]
    __nv_bfloat16* sWl = sWh + 9 * 16 * 64;                           // 9216 each

    const int b   = blockIdx.x;
    const int n   = b >> 8;             // 256 tiles per sample
    const int t   = b & 255;
    const int ty0 = (t >> 4) << 4;
    const int tx0 = (t & 15) << 4;
    const int tid = threadIdx.x;
    const int wid = tid >> 5;
    const int y0  = wid << 1;           // warp rows y0, y0+1

    wmma::fragment<wmma::accumulator, 16, 16, 16, float> acc[2][4];
#pragma unroll
    for (int y2 = 0; y2 < 2; y2++)
#pragma unroll
        for (int f = 0; f < 4; f++) wmma::fill_fragment(acc[y2][f], 0.f);

    const int nchunks = Cin >> 4;
    for (int cb = 0; cb < nchunks; cb++) {
        const int ci0 = cb << 4;
        __syncthreads();
        // stage patch [yy][xx][ci]: in(ty0+yy-1, tx0+xx-1), zero-padded
        for (int idx = tid; idx < 18 * 18 * 16; idx += 256) {
            int ci = idx & 15;
            int r  = idx >> 4;          // yy*18+xx
            int yy = r / 18;
            int xx = r - yy * 18;
            int gy = ty0 + yy - 1, gx = tx0 + xx - 1;
            float v = 0.f;
            if ((unsigned)gy < 256u && (unsigned)gx < 256u)
                v = x[(((size_t)(n * Cin + ci0 + ci)) << 16) + (gy << 8) + gx];
            __nv_bfloat16 h, l; split_bf16(v, h, l);
            sPh[idx] = h; sPl[idx] = l;
        }
        // stage weights [d][ci][oc]: w layout [O][Cin][3][3]
        for (int idx = tid; idx < 9 * 16 * 64; idx += 256) {
            int d  = idx >> 10;         // / 1024
            int r  = idx & 1023;
            int ci = r >> 6;
            int o  = r & 63;
            float v = w[(size_t)(o * Cin + ci0 + ci) * 9 + d];
            __nv_bfloat16 h, l; split_bf16(v, h, l);
            sWh[idx] = h; sWl[idx] = l;
        }
        __syncthreads();

#pragma unroll 1
        for (int d = 0; d < 9; d++) {
            const int ky = d / 3, kx = d - 3 * (d / 3);
            wmma::fragment<wmma::matrix_b, 16, 16, 16, __nv_bfloat16, wmma::row_major> bh[4], bl[4];
#pragma unroll
            for (int f = 0; f < 4; f++) {
                wmma::load_matrix_sync(bh[f], sWh + d * 1024 + f * 16, 64);
                wmma::load_matrix_sync(bl[f], sWl + d * 1024 + f * 16, 64);
            }
#pragma unroll
            for (int y2 = 0; y2 < 2; y2++) {
                const int off = ((y0 + y2 + ky) * 18 + kx) << 4;
                wmma::fragment<wmma::matrix_a, 16, 16, 16, __nv_bfloat16, wmma::row_major> ah, al;
                wmma::load_matrix_sync(ah, sPh + off, 16);
                wmma::load_matrix_sync(al, sPl + off, 16);
#pragma unroll
                for (int f = 0; f < 4; f++) {
                    wmma::mma_sync(acc[y2][f], ah, bh[f], acc[y2][f]);
                    wmma::mma_sync(acc[y2][f], ah, bl[f], acc[y2][f]);
                    wmma::mma_sync(acc[y2][f], al, bh[f], acc[y2][f]);
                }
            }
        }
    }

    // store: frag (m=x, n=oc) -> y1[oc][y][x]  => mem_col_major, ldm=65536
#pragma unroll
    for (int y2 = 0; y2 < 2; y2++)
#pragma unroll
        for (int f = 0; f < 4; f++) {
            float* p = g_y1 + (((size_t)(n * 64 + f * 16)) << 16)
                     + ((ty0 + y0 + y2) << 8) + tx0;
            wmma::store_matrix_sync(p, acc[y2][f], 65536, wmma::mem_col_major);
        }
}

// ---------------------------------------------------------------------------
// K2/K5: per-row (65536 elems) sum / sumsq. which=0 -> y1, which=1 -> z.
// ---------------------------------------------------------------------------
__global__ __launch_bounds__(256) void rowstat_kernel(int which)
{
    const float* buf = which ? g_z : g_y1;
    float* stat      = which ? g_stat2 : g_stat1;
    const int row = blockIdx.x;
    const float4* p = reinterpret_cast<const float4*>(buf + ((size_t)row << 16));
    float s = 0.f, q = 0.f;
    for (int i = threadIdx.x; i < 16384; i += 256) {
        float4 v = p[i];
        s += v.x + v.y + v.z + v.w;
        q += v.x * v.x + v.y * v.y + v.z * v.z + v.w * v.w;
    }
    __shared__ float rs[256], rq[256];
    rs[threadIdx.x] = s; rq[threadIdx.x] = q;
    __syncthreads();
    for (int st = 128; st > 0; st >>= 1) {
        if (threadIdx.x < st) {
            rs[threadIdx.x] += rs[threadIdx.x + st];
            rq[threadIdx.x] += rq[threadIdx.x + st];
        }
        __syncthreads();
    }
    if (threadIdx.x == 0) { stat[row * 2] = rs[0]; stat[row * 2 + 1] = rq[0]; }
}

// ---------------------------------------------------------------------------
// K3/K6: BN coefficients. h = relu(a*x + b). pooled => batch stats (0,2,3).
// ---------------------------------------------------------------------------
__global__ void bncoef_kernel(const float* __restrict__ gamma,
                              const float* __restrict__ beta,
                              int C, int pooled, int which)
{
    int t = blockIdx.x * blockDim.x + threadIdx.x;
    if (t >= 5 * C) return;
    const float* stat = which ? g_stat2 : g_stat1;
    float* A = which ? g_a2 : g_a1;
    float* B = which ? g_b2 : g_b1;
    int o = t % C;
    float mean, var;
    if (pooled) {
        float s = 0.f, q = 0.f;
        for (int m = 0; m < 5; m++) {
            s += stat[(m * C + o) * 2];
            q += stat[(m * C + o) * 2 + 1];
        }
        const float inv = 1.f / (5.f * 65536.f);
        mean = s * inv; var = q * inv - mean * mean;
    } else {
        const float inv = 1.f / 65536.f;
        mean = stat[t * 2] * inv; var = stat[t * 2 + 1] * inv - mean * mean;
    }
    float a = gamma[o] * rsqrtf(var + 1e-5f);
    A[t] = a;
    B[t] = fmaf(-mean, a, beta[o]);
}

// ---------------------------------------------------------------------------
// K4: wmma GEMM. Block tile M=128 oc x N=128 px, K=64 (4 stages of 16).
// A = w2 split, staged whole [128][64] (ld=64). B = relu(bn1(y1)) split,
// staged [16][128] per k-stage (ld=128). 8 warps as 4m x 2n:
// warp = 32 oc x 64 px = 2 m-frags x 4 n-frags.
// ---------------------------------------------------------------------------
__global__ __launch_bounds__(256) void gemm_wmma_kernel(const float* __restrict__ w2)
{
    __shared__ __nv_bfloat16 sAh[128 * 64];    // 16 KB
    __shared__ __nv_bfloat16 sAl[128 * 64];    // 16 KB
    __shared__ __nv_bfloat16 sBh[16 * 128];    // 4 KB
    __shared__ __nv_bfloat16 sBl[16 * 128];    // 4 KB
    __shared__ float s_a[64], s_b[64];

    const int blk = blockIdx.x;
    const int n   = blk >> 9;            // 512 pixel tiles per sample
    const int p0  = (blk & 511) << 7;
    const int tid = threadIdx.x;
    const int wid = tid >> 5;
    const int warp_m = wid & 3;          // 32-oc slice
    const int warp_n = wid >> 2;         // 64-px slice

    if (tid < 64) { s_a[tid] = g_a1[n * 64 + tid]; s_b[tid] = g_b1[n * 64 + tid]; }

    // stage A = w2 split: [oc][k], ld=64
    for (int idx = tid; idx < 128 * 64; idx += 256) {
        __nv_bfloat16 h, l; split_bf16(w2[idx], h, l);
        sAh[idx] = h; sAl[idx] = l;
    }

    wmma::fragment<wmma::accumulator, 16, 16, 16, float> acc[2][4];
#pragma unroll
    for (int mi = 0; mi < 2; mi++)
#pragma unroll
        for (int j = 0; j < 4; j++) wmma::fill_fragment(acc[mi][j], 0.f);

    for (int ks = 0; ks < 4; ks++) {
        const int k0 = ks << 4;
        __syncthreads();
        // stage B: h = relu(a*y1+b) for k rows k0..k0+15, 128 px
        for (int idx = tid; idx < 16 * 32; idx += 256) {   // float4 granules
            int kk = idx >> 5;
            int p4 = (idx & 31) << 2;
            int o  = k0 + kk;
            float4 v = *reinterpret_cast<const float4*>(
                g_y1 + (((size_t)(n * 64 + o)) << 16) + p0 + p4);
            float a = s_a[o], bb = s_b[o];
            float hv[4] = { fmaxf(fmaf(a, v.x, bb), 0.f), fmaxf(fmaf(a, v.y, bb), 0.f),
                            fmaxf(fmaf(a, v.z, bb), 0.f), fmaxf(fmaf(a, v.w, bb), 0.f) };
#pragma unroll
            for (int q = 0; q < 4; q++) {
                __nv_bfloat16 h, l; split_bf16(hv[q], h, l);
                sBh[(kk << 7) + p4 + q] = h;
                sBl[(kk << 7) + p4 + q] = l;
            }
        }
        __syncthreads();

        wmma::fragment<wmma::matrix_a, 16, 16, 16, __nv_bfloat16, wmma::row_major> ah[2], al[2];
#pragma unroll
        for (int mi = 0; mi < 2; mi++) {
            const int oc = (warp_m << 5) + (mi << 4);
            wmma::load_matrix_sync(ah[mi], sAh + oc * 64 + k0, 64);
            wmma::load_matrix_sync(al[mi], sAl + oc * 64 + k0, 64);
        }
#pragma unroll
        for (int j = 0; j < 4; j++) {
            wmma::fragment<wmma::matrix_b, 16, 16, 16, __nv_bfloat16, wmma::row_major> bh, bl;
            const int px = (warp_n << 6) + (j << 4);
            wmma::load_matrix_sync(bh, sBh + px, 128);
            wmma::load_matrix_sync(bl, sBl + px, 128);
#pragma unroll
            for (int mi = 0; mi < 2; mi++) {
                wmma::mma_sync(acc[mi][j], ah[mi], bh, acc[mi][j]);
                wmma::mma_sync(acc[mi][j], ah[mi], bl, acc[mi][j]);
                wmma::mma_sync(acc[mi][j], al[mi], bh, acc[mi][j]);
            }
        }
    }

    // store: frag (m=oc, n=px) -> z[oc][px]  => mem_row_major, ldm=65536
#pragma unroll
    for (int mi = 0; mi < 2; mi++)
#pragma unroll
        for (int j = 0; j < 4; j++) {
            const int oc = (warp_m << 5) + (mi << 4);
            float* p = g_z + (((size_t)(n * 128 + oc)) << 16)
                     + p0 + (warp_n << 6) + (j << 4);
            wmma::store_matrix_sync(p, acc[mi][j], 65536, wmma::mem_row_major);
        }
}

// ---------------------------------------------------------------------------
// K7: feat[e][row] = mean_pix relu(a2*z + b2)   (row = n*128+oc)
// ---------------------------------------------------------------------------
__global__ __launch_bounds__(256) void feat_kernel(int e)
{
    const int row = blockIdx.x;   // 0..639
    const float a = g_a2[row], b = g_b2[row];
    const float4* p = reinterpret_cast<const float4*>(g_z + ((size_t)row << 16));
    float s = 0.f;
    for (int i = threadIdx.x; i < 16384; i += 256) {
        float4 v = p[i];
        s += fmaxf(fmaf(a, v.x, b), 0.f) + fmaxf(fmaf(a, v.y, b), 0.f)
           + fmaxf(fmaf(a, v.z, b), 0.f) + fmaxf(fmaf(a, v.w, b), 0.f);
    }
    __shared__ float rs[256];
    rs[threadIdx.x] = s;
    __syncthreads();
    for (int st = 128; st > 0; st >>= 1) {
        if (threadIdx.x < st) rs[threadIdx.x] += rs[threadIdx.x + st];
        __syncthreads();
    }
    if (threadIdx.x == 0) g_feat[e * 640 + row] = rs[0] * (1.f / 65536.f);
}

// ---------------------------------------------------------------------------
// K8: normalize features, similarity logits, masked logsumexp CE, weighted avg
// ---------------------------------------------------------------------------
__global__ void loss_kernel(const int* __restrict__ mask, float* __restrict__ out)
{
    __shared__ float Q[3][5][128];
    __shared__ float Kf[3][5][128];
    __shared__ float S[3][5][5];
    __shared__ float X[3][5][3];
    __shared__ int cnt[12];
    __shared__ float wls[15], wts[15];
    const int tid = threadIdx.x;

    if (tid < 30) {                       // normalize: 30 feature rows
        int path = tid / 15;
        int r = tid % 15;
        int g = r / 5, i = r % 5;
        const float* f = g_feat + ((path * 3 + g) * 5 + i) * 128;
        float nr = 0.f;
        for (int d = 0; d < 128; d++) nr += f[d] * f[d];
        float inv = 1.f / fmaxf(sqrtf(nr), 1e-12f);
        float* dst = path ? &Kf[g][i][0] : &Q[g][i][0];
        for (int d = 0; d < 128; d++) dst[d] = f[d] * inv;
    }
    if (tid < 12) cnt[tid] = 0;
    __syncthreads();

    // decision_mask counts: cnt[g][agent]
    for (int idx = tid; idx < 4 * 128 * 128; idx += blockDim.x) {
        int m = mask[idx];
        if (m >= 1) atomicAdd(&cnt[(m - 1) * 4 + (idx >> 14)], 1);
    }

    if (tid < 75) {                       // S[g,i,j] = Q[g,i].K[g,j]
        int g = tid / 25, i = (tid % 25) / 5, j = tid % 5;
        float s = 0.f;
        for (int d = 0; d < 128; d++) s += Q[g][i][d] * Kf[g][j][d];
        S[g][i][j] = s;
    } else if (tid < 120) {               // X[g,i,h] = Q[g,i].K[h,i]
        int r = tid - 75;
        int g = r / 15, i = (r % 15) / 3, h = r % 3;
        float s = 0.f;
        for (int d = 0; d < 128; d++) s += Q[g][i][d] * Kf[h][i][d];
        X[g][i][h] = s;
    }
    __syncthreads();

    if (tid < 15) {
        int g = tid / 5, i = tid % 5;
        float lg[9];
        lg[0] = S[g][i][i];
        for (int j = 0; j < 5; j++) lg[1 + j] = (j == i) ? -1e9f : S[g][i][j];
        for (int h = 0; h < 3; h++) lg[6 + h] = (h == g) ? -1e9f : X[g][i][h];
        float mx = -3.4e38f;
        for (int r = 0; r < 9; r++) { lg[r] *= 10.f; mx = fmaxf(mx, lg[r]); }  // /TEMP
        float se = 0.f;
        for (int r = 0; r < 9; r++) se += expf(lg[r] - mx);
        float lse = mx + logf(se);
        float lt = lse - lg[0];
        float wgt = (i == 0) ? 0.f : (float)cnt[g * 4 + i - 1];
        wls[tid] = wgt * lt;
        wts[tid] = wgt;
    }
    __syncthreads();
    if (tid == 0) {
        float ws = 0.f, tot = 0.f;
        for (int r = 0; r < 15; r++) { ws += wls[r]; tot += wts[r]; }
        out[0] = (tot > 0.f) ? (ws / fmaxf(tot, 1.f)) : 0.f;
    }
}

// ---------------------------------------------------------------------------
extern "C" void kernel_launch(void* const* d_in, const int* in_sizes, int n_in,
                              void* d_out, int out_size)
{
    (void)in_sizes; (void)n_in; (void)out_size;
    const int CONV_SMEM = (2 * 18 * 18 * 16 + 2 * 9 * 16 * 64) * 2;  // 57600 B
    static int attr_done = 0;
    if (!attr_done) {
        cudaFuncSetAttribute(conv3x3_wmma_kernel,
                             cudaFuncAttributeMaxDynamicSharedMemorySize, CONV_SMEM);
        attr_done = 1;
    }

    const int Cin[3] = {64, 32, 16};
    for (int path = 0; path < 2; path++) {
        for (int g = 0; g < 3; g++) {
            const float* x  = (const float*)d_in[g * 8 + path];   // 0:sparse 1:dense
            const float* w1 = (const float*)d_in[g * 8 + 2];
            const float* g1 = (const float*)d_in[g * 8 + 3];
            const float* b1 = (const float*)d_in[g * 8 + 4];
            const float* w2 = (const float*)d_in[g * 8 + 5];
            const float* g2 = (const float*)d_in[g * 8 + 6];
            const float* b2 = (const float*)d_in[g * 8 + 7];

            conv3x3_wmma_kernel<<<1280, 256, CONV_SMEM>>>(x, w1, Cin[g]);
            rowstat_kernel<<<320, 256>>>(0);
            bncoef_kernel<<<2, 256>>>(g1, b1, 64, path, 0);
            gemm_wmma_kernel<<<2560, 256>>>(w2);
            rowstat_kernel<<<640, 256>>>(1);
            bncoef_kernel<<<3, 256>>>(g2, b2, 128, path, 1);
            feat_kernel<<<640, 256>>>(path * 3 + g);
        }
    }
    loss_kernel<<<1, 256>>>((const int*)d_in[24], (float*)d_out);
}

// round 12
// speedup vs baseline: 1.5244x; 1.5244x over previous
#include <cuda_runtime.h>
#include <cuda_bf16.h>
#include <mma.h>
#include <cstdint>

using namespace nvcuda;

// ---------------------------------------------------------------------------
// ContrastiveSparsityLoss — wmma bf16-split (HMMA) conv + GEMM.
// tcgen05 unavailable (harness targets compute_103 without 'a' features);
// wmma/mma.sync bf16 is base-PTX and runs on the tensor pipe.
//
// R12: de-conflict all fragment loads. Every smem tile leading dimension is
// padded to an odd multiple of 16B so ldmatrix row addresses advance through
// distinct bank phases (gemm A ld 64->72, gemm B 128->136, conv patch ci
// 16->24, conv weights oc 64->72).
// ---------------------------------------------------------------------------

__device__ float g_y1[5 * 64 * 65536];    // 83.9 MB scratch
__device__ float g_z [5 * 128 * 65536];   // 167.8 MB scratch
__device__ float g_stat1[5 * 64 * 2];
__device__ float g_stat2[5 * 128 * 2];
__device__ float g_a1[5 * 64];
__device__ float g_b1[5 * 64];
__device__ float g_a2[5 * 128];
__device__ float g_b2[5 * 128];
__device__ float g_feat[6 * 5 * 128];     // [e][n][oc], e = path*3+g

__device__ __forceinline__ void split_bf16(float v, __nv_bfloat16& hi, __nv_bfloat16& lo) {
    hi = __float2bfloat16(v);
    lo = __float2bfloat16(v - __bfloat162float(hi));
}

// ---------------------------------------------------------------------------
// K1: conv3x3 SAME via wmma. Block = 64 oc x 16x16 pixel tile of one sample.
// 8 warps; warp owns 2 y-rows x all 64 oc. For each (dy,dx) tap the conv is
// a [x16 x ci16] @ [ci16 x oc16] GEMM on a shifted patch window.
// Patch [yy][xx][ci24] (lda=24 -> 48B row stride, conflict-free ldmatrix).
// Weights [d][ci16][oc72]  (ldb=72 -> 144B row stride, conflict-free).
// 3-term bf16 split: acc += Ah*Bh + Ah*Bl + Al*Bh.
// ---------------------------------------------------------------------------
#define CPAD 24
#define WPAD 72
__global__ __launch_bounds__(256) void conv3x3_wmma_kernel(
    const float* __restrict__ x, const float* __restrict__ w, int Cin)
{
    extern __shared__ char dynsmem[];
    __nv_bfloat16* sPh = reinterpret_cast<__nv_bfloat16*>(dynsmem);   // [18][18][24]
    __nv_bfloat16* sPl = sPh + 18 * 18 * CPAD;
    __nv_bfloat16* sWh = sPl + 18 * 18 * CPAD;                        // [9][16][72]
    __nv_bfloat16* sWl = sWh + 9 * 16 * WPAD;

    const int b   = blockIdx.x;
    const int n   = b >> 8;             // 256 tiles per sample
    const int t   = b & 255;
    const int ty0 = (t >> 4) << 4;
    const int tx0 = (t & 15) << 4;
    const int tid = threadIdx.x;
    const int wid = tid >> 5;
    const int y0  = wid << 1;           // warp rows y0, y0+1

    wmma::fragment<wmma::accumulator, 16, 16, 16, float> acc[2][4];
#pragma unroll
    for (int y2 = 0; y2 < 2; y2++)
#pragma unroll
        for (int f = 0; f < 4; f++) wmma::fill_fragment(acc[y2][f], 0.f);

    const int nchunks = Cin >> 4;
    for (int cb = 0; cb < nchunks; cb++) {
        const int ci0 = cb << 4;
        __syncthreads();
        // stage patch [yy][xx][ci]: in(ty0+yy-1, tx0+xx-1), zero-padded
        for (int idx = tid; idx < 18 * 18 * 16; idx += 256) {
            int ci = idx & 15;
            int r  = idx >> 4;          // yy*18+xx
            int yy = r / 18;
            int xx = r - yy * 18;
            int gy = ty0 + yy - 1, gx = tx0 + xx - 1;
            float v = 0.f;
            if ((unsigned)gy < 256u && (unsigned)gx < 256u)
                v = x[(((size_t)(n * Cin + ci0 + ci)) << 16) + (gy << 8) + gx];
            __nv_bfloat16 h, l; split_bf16(v, h, l);
            sPh[r * CPAD + ci] = h; sPl[r * CPAD + ci] = l;
        }
        // stage weights [d][ci][oc]: w layout [O][Cin][3][3]
        for (int idx = tid; idx < 9 * 16 * 64; idx += 256) {
            int d  = idx >> 10;         // / 1024
            int r  = idx & 1023;
            int ci = r >> 6;
            int o  = r & 63;
            float v = w[(size_t)(o * Cin + ci0 + ci) * 9 + d];
            __nv_bfloat16 h, l; split_bf16(v, h, l);
            sWh[(d * 16 + ci) * WPAD + o] = h;
            sWl[(d * 16 + ci) * WPAD + o] = l;
        }
        __syncthreads();

#pragma unroll 1
        for (int d = 0; d < 9; d++) {
            const int ky = d / 3, kx = d - 3 * (d / 3);
            wmma::fragment<wmma::matrix_b, 16, 16, 16, __nv_bfloat16, wmma::row_major> bh[4], bl[4];
#pragma unroll
            for (int f = 0; f < 4; f++) {
                wmma::load_matrix_sync(bh[f], sWh + d * 16 * WPAD + f * 16, WPAD);
                wmma::load_matrix_sync(bl[f], sWl + d * 16 * WPAD + f * 16, WPAD);
            }
#pragma unroll
            for (int y2 = 0; y2 < 2; y2++) {
                const int off = ((y0 + y2 + ky) * 18 + kx) * CPAD;
                wmma::fragment<wmma::matrix_a, 16, 16, 16, __nv_bfloat16, wmma::row_major> ah, al;
                wmma::load_matrix_sync(ah, sPh + off, CPAD);
                wmma::load_matrix_sync(al, sPl + off, CPAD);
#pragma unroll
                for (int f = 0; f < 4; f++) {
                    wmma::mma_sync(acc[y2][f], ah, bh[f], acc[y2][f]);
                    wmma::mma_sync(acc[y2][f], ah, bl[f], acc[y2][f]);
                    wmma::mma_sync(acc[y2][f], al, bh[f], acc[y2][f]);
                }
            }
        }
    }

    // store: frag (m=x, n=oc) -> y1[oc][y][x]  => mem_col_major, ldm=65536
#pragma unroll
    for (int y2 = 0; y2 < 2; y2++)
#pragma unroll
        for (int f = 0; f < 4; f++) {
            float* p = g_y1 + (((size_t)(n * 64 + f * 16)) << 16)
                     + ((ty0 + y0 + y2) << 8) + tx0;
            wmma::store_matrix_sync(p, acc[y2][f], 65536, wmma::mem_col_major);
        }
}

// ---------------------------------------------------------------------------
// K2/K5: per-row (65536 elems) sum / sumsq. which=0 -> y1, which=1 -> z.
// ---------------------------------------------------------------------------
__global__ __launch_bounds__(256) void rowstat_kernel(int which)
{
    const float* buf = which ? g_z : g_y1;
    float* stat      = which ? g_stat2 : g_stat1;
    const int row = blockIdx.x;
    const float4* p = reinterpret_cast<const float4*>(buf + ((size_t)row << 16));
    float s = 0.f, q = 0.f;
    for (int i = threadIdx.x; i < 16384; i += 256) {
        float4 v = p[i];
        s += v.x + v.y + v.z + v.w;
        q += v.x * v.x + v.y * v.y + v.z * v.z + v.w * v.w;
    }
    __shared__ float rs[256], rq[256];
    rs[threadIdx.x] = s; rq[threadIdx.x] = q;
    __syncthreads();
    for (int st = 128; st > 0; st >>= 1) {
        if (threadIdx.x < st) {
            rs[threadIdx.x] += rs[threadIdx.x + st];
            rq[threadIdx.x] += rq[threadIdx.x + st];
        }
        __syncthreads();
    }
    if (threadIdx.x == 0) { stat[row * 2] = rs[0]; stat[row * 2 + 1] = rq[0]; }
}

// ---------------------------------------------------------------------------
// K3/K6: BN coefficients. h = relu(a*x + b). pooled => batch stats (0,2,3).
// ---------------------------------------------------------------------------
__global__ void bncoef_kernel(const float* __restrict__ gamma,
                              const float* __restrict__ beta,
                              int C, int pooled, int which)
{
    int t = blockIdx.x * blockDim.x + threadIdx.x;
    if (t >= 5 * C) return;
    const float* stat = which ? g_stat2 : g_stat1;
    float* A = which ? g_a2 : g_a1;
    float* B = which ? g_b2 : g_b1;
    int o = t % C;
    float mean, var;
    if (pooled) {
        float s = 0.f, q = 0.f;
        for (int m = 0; m < 5; m++) {
            s += stat[(m * C + o) * 2];
            q += stat[(m * C + o) * 2 + 1];
        }
        const float inv = 1.f / (5.f * 65536.f);
        mean = s * inv; var = q * inv - mean * mean;
    } else {
        const float inv = 1.f / 65536.f;
        mean = stat[t * 2] * inv; var = stat[t * 2 + 1] * inv - mean * mean;
    }
    float a = gamma[o] * rsqrtf(var + 1e-5f);
    A[t] = a;
    B[t] = fmaf(-mean, a, beta[o]);
}

// ---------------------------------------------------------------------------
// K4: wmma GEMM. Block tile M=128 oc x N=128 px, K=64 (4 stages of 16).
// A = w2 split, staged whole [128][72] (ld=72, conflict-free).
// B = relu(bn1(y1)) split, staged [16][136] per k-stage (ld=136).
// 8 warps as 4m x 2n: warp = 32 oc x 64 px = 2 m-frags x 4 n-frags.
// ---------------------------------------------------------------------------
#define APAD 72
#define BPAD 136
__global__ __launch_bounds__(256) void gemm_wmma_kernel(const float* __restrict__ w2)
{
    __shared__ __nv_bfloat16 sAh[128 * APAD];   // 18.0 KB
    __shared__ __nv_bfloat16 sAl[128 * APAD];   // 18.0 KB
    __shared__ __nv_bfloat16 sBh[16 * BPAD];    // 4.25 KB
    __shared__ __nv_bfloat16 sBl[16 * BPAD];    // 4.25 KB
    __shared__ float s_a[64], s_b[64];

    const int blk = blockIdx.x;
    const int n   = blk >> 9;            // 512 pixel tiles per sample
    const int p0  = (blk & 511) << 7;
    const int tid = threadIdx.x;
    const int wid = tid >> 5;
    const int warp_m = wid & 3;          // 32-oc slice
    const int warp_n = wid >> 2;         // 64-px slice

    if (tid < 64) { s_a[tid] = g_a1[n * 64 + tid]; s_b[tid] = g_b1[n * 64 + tid]; }

    // stage A = w2 split: [oc][k], ld=APAD
    for (int idx = tid; idx < 128 * 64; idx += 256) {
        int oc = idx >> 6, k = idx & 63;
        __nv_bfloat16 h, l; split_bf16(w2[idx], h, l);
        sAh[oc * APAD + k] = h; sAl[oc * APAD + k] = l;
    }

    wmma::fragment<wmma::accumulator, 16, 16, 16, float> acc[2][4];
#pragma unroll
    for (int mi = 0; mi < 2; mi++)
#pragma unroll
        for (int j = 0; j < 4; j++) wmma::fill_fragment(acc[mi][j], 0.f);

    for (int ks = 0; ks < 4; ks++) {
        const int k0 = ks << 4;
        __syncthreads();
        // stage B: h = relu(a*y1+b) for k rows k0..k0+15, 128 px
        for (int idx = tid; idx < 16 * 32; idx += 256) {   // float4 granules
            int kk = idx >> 5;
            int p4 = (idx & 31) << 2;
            int o  = k0 + kk;
            float4 v = *reinterpret_cast<const float4*>(
                g_y1 + (((size_t)(n * 64 + o)) << 16) + p0 + p4);
            float a = s_a[o], bb = s_b[o];
            float hv[4] = { fmaxf(fmaf(a, v.x, bb), 0.f), fmaxf(fmaf(a, v.y, bb), 0.f),
                            fmaxf(fmaf(a, v.z, bb), 0.f), fmaxf(fmaf(a, v.w, bb), 0.f) };
#pragma unroll
            for (int q = 0; q < 4; q++) {
                __nv_bfloat16 h, l; split_bf16(hv[q], h, l);
                sBh[kk * BPAD + p4 + q] = h;
                sBl[kk * BPAD + p4 + q] = l;
            }
        }
        __syncthreads();

        wmma::fragment<wmma::matrix_a, 16, 16, 16, __nv_bfloat16, wmma::row_major> ah[2], al[2];
#pragma unroll
        for (int mi = 0; mi < 2; mi++) {
            const int oc = (warp_m << 5) + (mi << 4);
            wmma::load_matrix_sync(ah[mi], sAh + oc * APAD + k0, APAD);
            wmma::load_matrix_sync(al[mi], sAl + oc * APAD + k0, APAD);
        }
#pragma unroll
        for (int j = 0; j < 4; j++) {
            wmma::fragment<wmma::matrix_b, 16, 16, 16, __nv_bfloat16, wmma::row_major> bh, bl;
            const int px = (warp_n << 6) + (j << 4);
            wmma::load_matrix_sync(bh, sBh + px, BPAD);
            wmma::load_matrix_sync(bl, sBl + px, BPAD);
#pragma unroll
            for (int mi = 0; mi < 2; mi++) {
                wmma::mma_sync(acc[mi][j], ah[mi], bh, acc[mi][j]);
                wmma::mma_sync(acc[mi][j], ah[mi], bl, acc[mi][j]);
                wmma::mma_sync(acc[mi][j], al[mi], bh, acc[mi][j]);
            }
        }
    }

    // store: frag (m=oc, n=px) -> z[oc][px]  => mem_row_major, ldm=65536
#pragma unroll
    for (int mi = 0; mi < 2; mi++)
#pragma unroll
        for (int j = 0; j < 4; j++) {
            const int oc = (warp_m << 5) + (mi << 4);
            float* p = g_z + (((size_t)(n * 128 + oc)) << 16)
                     + p0 + (warp_n << 6) + (j << 4);
            wmma::store_matrix_sync(p, acc[mi][j], 65536, wmma::mem_row_major);
        }
}

// ---------------------------------------------------------------------------
// K7: feat[e][row] = mean_pix relu(a2*z + b2)   (row = n*128+oc)
// ---------------------------------------------------------------------------
__global__ __launch_bounds__(256) void feat_kernel(int e)
{
    const int row = blockIdx.x;   // 0..639
    const float a = g_a2[row], b = g_b2[row];
    const float4* p = reinterpret_cast<const float4*>(g_z + ((size_t)row << 16));
    float s = 0.f;
    for (int i = threadIdx.x; i < 16384; i += 256) {
        float4 v = p[i];
        s += fmaxf(fmaf(a, v.x, b), 0.f) + fmaxf(fmaf(a, v.y, b), 0.f)
           + fmaxf(fmaf(a, v.z, b), 0.f) + fmaxf(fmaf(a, v.w, b), 0.f);
    }
    __shared__ float rs[256];
    rs[threadIdx.x] = s;
    __syncthreads();
    for (int st = 128; st > 0; st >>= 1) {
        if (threadIdx.x < st) rs[threadIdx.x] += rs[threadIdx.x + st];
        __syncthreads();
    }
    if (threadIdx.x == 0) g_feat[e * 640 + row] = rs[0] * (1.f / 65536.f);
}

// ---------------------------------------------------------------------------
// K8: normalize features, similarity logits, masked logsumexp CE, weighted avg
// ---------------------------------------------------------------------------
__global__ void loss_kernel(const int* __restrict__ mask, float* __restrict__ out)
{
    __shared__ float Q[3][5][128];
    __shared__ float Kf[3][5][128];
    __shared__ float S[3][5][5];
    __shared__ float X[3][5][3];
    __shared__ int cnt[12];
    __shared__ float wls[15], wts[15];
    const int tid = threadIdx.x;

    if (tid < 30) {                       // normalize: 30 feature rows
        int path = tid / 15;
        int r = tid % 15;
        int g = r / 5, i = r % 5;
        const float* f = g_feat + ((path * 3 + g) * 5 + i) * 128;
        float nr = 0.f;
        for (int d = 0; d < 128; d++) nr += f[d] * f[d];
        float inv = 1.f / fmaxf(sqrtf(nr), 1e-12f);
        float* dst = path ? &Kf[g][i][0] : &Q[g][i][0];
        for (int d = 0; d < 128; d++) dst[d] = f[d] * inv;
    }
    if (tid < 12) cnt[tid] = 0;
    __syncthreads();

    // decision_mask counts: cnt[g][agent]
    for (int idx = tid; idx < 4 * 128 * 128; idx += blockDim.x) {
        int m = mask[idx];
        if (m >= 1) atomicAdd(&cnt[(m - 1) * 4 + (idx >> 14)], 1);
    }

    if (tid < 75) {                       // S[g,i,j] = Q[g,i].K[g,j]
        int g = tid / 25, i = (tid % 25) / 5, j = tid % 5;
        float s = 0.f;
        for (int d = 0; d < 128; d++) s += Q[g][i][d] * Kf[g][j][d];
        S[g][i][j] = s;
    } else if (tid < 120) {               // X[g,i,h] = Q[g,i].K[h,i]
        int r = tid - 75;
        int g = r / 15, i = (r % 15) / 3, h = r % 3;
        float s = 0.f;
        for (int d = 0; d < 128; d++) s += Q[g][i][d] * Kf[h][i][d];
        X[g][i][h] = s;
    }
    __syncthreads();

    if (tid < 15) {
        int g = tid / 5, i = tid % 5;
        float lg[9];
        lg[0] = S[g][i][i];
        for (int j = 0; j < 5; j++) lg[1 + j] = (j == i) ? -1e9f : S[g][i][j];
        for (int h = 0; h < 3; h++) lg[6 + h] = (h == g) ? -1e9f : X[g][i][h];
        float mx = -3.4e38f;
        for (int r = 0; r < 9; r++) { lg[r] *= 10.f; mx = fmaxf(mx, lg[r]); }  // /TEMP
        float se = 0.f;
        for (int r = 0; r < 9; r++) se += expf(lg[r] - mx);
        float lse = mx + logf(se);
        float lt = lse - lg[0];
        float wgt = (i == 0) ? 0.f : (float)cnt[g * 4 + i - 1];
        wls[tid] = wgt * lt;
        wts[tid] = wgt;
    }
    __syncthreads();
    if (tid == 0) {
        float ws = 0.f, tot = 0.f;
        for (int r = 0; r < 15; r++) { ws += wls[r]; tot += wts[r]; }
        out[0] = (tot > 0.f) ? (ws / fmaxf(tot, 1.f)) : 0.f;
    }
}

// ---------------------------------------------------------------------------
extern "C" void kernel_launch(void* const* d_in, const int* in_sizes, int n_in,
                              void* d_out, int out_size)
{
    (void)in_sizes; (void)n_in; (void)out_size;
    const int CONV_SMEM = (2 * 18 * 18 * CPAD + 2 * 9 * 16 * WPAD) * 2;  // 72576 B
    static int attr_done = 0;
    if (!attr_done) {
        cudaFuncSetAttribute(conv3x3_wmma_kernel,
                             cudaFuncAttributeMaxDynamicSharedMemorySize, CONV_SMEM);
        attr_done = 1;
    }

    const int Cin[3] = {64, 32, 16};
    for (int path = 0; path < 2; path++) {
        for (int g = 0; g < 3; g++) {
            const float* x  = (const float*)d_in[g * 8 + path];   // 0:sparse 1:dense
            const float* w1 = (const float*)d_in[g * 8 + 2];
            const float* g1 = (const float*)d_in[g * 8 + 3];
            const float* b1 = (const float*)d_in[g * 8 + 4];
            const float* w2 = (const float*)d_in[g * 8 + 5];
            const float* g2 = (const float*)d_in[g * 8 + 6];
            const float* b2 = (const float*)d_in[g * 8 + 7];

            conv3x3_wmma_kernel<<<1280, 256, CONV_SMEM>>>(x, w1, Cin[g]);
            rowstat_kernel<<<320, 256>>>(0);
            bncoef_kernel<<<2, 256>>>(g1, b1, 64, path, 0);
            gemm_wmma_kernel<<<2560, 256>>>(w2);
            rowstat_kernel<<<640, 256>>>(1);
            bncoef_kernel<<<3, 256>>>(g2, b2, 128, path, 1);
            feat_kernel<<<640, 256>>>(path * 3 + g);
        }
    }
    loss_kernel<<<1, 256>>>((const int*)d_in[24], (float*)d_out);
}